// round 1
// baseline (speedup 1.0000x reference)
#include <cuda_runtime.h>
#include <math.h>

#define BB   2048
#define NN   36
#define EMBD 1024
#define SIMD 16
#define HID  32
#define KK   8

// Folded head parameters (written by prep kernel each launch — deterministic).
__device__ float g_Wc[SIMD * HID];   // Wc[d][h] = sum_j (sum_k gcn_w[k][d][j]) * W1[h][j]
__device__ float g_b1[HID];
__device__ float g_w2[HID];
__device__ float g_b2;

__global__ void prep_kernel(const float* __restrict__ gcn_w,
                            const float* __restrict__ out1_v,
                            const float* __restrict__ out1_g,
                            const float* __restrict__ out1_b,
                            const float* __restrict__ out2_v,
                            const float* __restrict__ out2_g,
                            const float* __restrict__ out2_b) {
    int h = threadIdx.x;  // 0..31
    if (h >= HID) return;

    // weight-norm row h of out1_v: W1[h][j] = g[h]*v[h][j]/(||v[h,:]||+1e-12)
    float nrm = 0.f;
    #pragma unroll
    for (int j = 0; j < HID; j++) { float v = out1_v[h * HID + j]; nrm += v * v; }
    float scale = out1_g[h] / (sqrtf(nrm) + 1e-12f);

    for (int d = 0; d < SIMD; d++) {
        float acc = 0.f;
        #pragma unroll
        for (int j = 0; j < HID; j++) {
            float ws = 0.f;
            #pragma unroll
            for (int k = 0; k < KK; k++) ws += gcn_w[(k * SIMD + d) * HID + j];
            acc += ws * out1_v[h * HID + j];
        }
        g_Wc[d * HID + h] = acc * scale;
    }
    g_b1[h] = out1_b[h];

    float n2 = 0.f;
    #pragma unroll
    for (int j = 0; j < HID; j++) { float v = out2_v[j]; n2 += v * v; }
    g_w2[h] = out2_g[0] * out2_v[h] / (sqrtf(n2) + 1e-12f);
    if (h == 0) g_b2 = out2_b[0];
}

__global__ __launch_bounds__(512, 2)
void simgsmn_main(const float* __restrict__ inp1,
                  const float* __restrict__ inp2,
                  float* __restrict__ out) {
    const int b    = blockIdx.x;
    const int tid  = threadIdx.x;
    const int lane = tid & 31;
    const int warp = tid >> 5;

    __shared__ float s_sim[NN][SIMD];
    __shared__ float s_Wc[SIMD * HID];
    __shared__ float s_b1[HID];
    __shared__ float s_w2[HID];
    __shared__ float s_partial[16];

    // stage folded weights into smem (512 threads == 512 Wc entries)
    s_Wc[tid] = g_Wc[tid];
    if (tid < HID) { s_b1[tid] = g_b1[tid]; s_w2[tid] = g_w2[tid]; }

    const float* p1 = inp1 + (size_t)b * (NN * EMBD);
    const float* p2 = inp2 + (size_t)b * (NN * EMBD);

    // ---- phase 1: block-wise cosine sim -> s_sim[i][d] ----
    // 512 threads = 2 rows * 16 d-blocks * 16 threads. Each thread: one float4
    // from each input. Warp covers 512 contiguous bytes -> fully coalesced.
    #pragma unroll 3
    for (int it = 0; it < NN / 2; it++) {
        const int i   = 2 * it + (tid >> 8);
        const int off = i * EMBD + (tid & 255) * 4;

        const float4 q = *reinterpret_cast<const float4*>(p1 + off);
        const float4 c = *reinterpret_cast<const float4*>(p2 + off);

        float dqc = q.x * c.x + q.y * c.y + q.z * c.z + q.w * c.w;
        float nq  = q.x * q.x + q.y * q.y + q.z * q.z + q.w * q.w;
        float nc  = c.x * c.x + c.y * c.y + c.z * c.z + c.w * c.w;

        #pragma unroll
        for (int o = 8; o > 0; o >>= 1) {
            dqc += __shfl_xor_sync(0xFFFFFFFFu, dqc, o);
            nq  += __shfl_xor_sync(0xFFFFFFFFu, nq,  o);
            nc  += __shfl_xor_sync(0xFFFFFFFFu, nc,  o);
        }
        if ((lane & 15) == 0) {
            const int d = (tid & 255) >> 4;
            s_sim[i][d] = dqc / ((sqrtf(nq) + 1e-8f) * (sqrtf(nc) + 1e-8f));
        }
    }
    __syncthreads();

    // ---- phase 2: per-row MLP head, warp per row ----
    float wsum = 0.f;
    for (int i = warp; i < NN; i += 16) {
        float acc = s_b1[lane];
        #pragma unroll
        for (int d = 0; d < SIMD; d++)
            acc += s_sim[i][d] * s_Wc[d * HID + lane];
        float p = tanhf(acc) * s_w2[lane];
        #pragma unroll
        for (int o = 16; o > 0; o >>= 1)
            p += __shfl_xor_sync(0xFFFFFFFFu, p, o);
        wsum += p;  // all lanes hold row sum; only lane 0's copy is used
    }
    if (lane == 0) s_partial[warp] = wsum;
    __syncthreads();

    if (warp == 0) {
        float v = (lane < 16) ? s_partial[lane] : 0.f;
        #pragma unroll
        for (int o = 16; o > 0; o >>= 1)
            v += __shfl_xor_sync(0xFFFFFFFFu, v, o);
        if (lane == 0) out[b] = v * (1.0f / NN) + g_b2;
    }
}

extern "C" void kernel_launch(void* const* d_in, const int* in_sizes, int n_in,
                              void* d_out, int out_size) {
    const float* inp1   = (const float*)d_in[0];
    const float* inp2   = (const float*)d_in[1];
    // d_in[2]=gk_mean, d_in[3]=gk_prec: unused — Gaussian branch collapses to
    // sum_j w_norm = S/(S+1e-8) = 1 - O(1e-7), below output tolerance.
    const float* gcn_w  = (const float*)d_in[4];
    const float* out1_v = (const float*)d_in[5];
    const float* out1_g = (const float*)d_in[6];
    const float* out1_b = (const float*)d_in[7];
    const float* out2_v = (const float*)d_in[8];
    const float* out2_g = (const float*)d_in[9];
    const float* out2_b = (const float*)d_in[10];
    float* out = (float*)d_out;

    prep_kernel<<<1, HID>>>(gcn_w, out1_v, out1_g, out1_b, out2_v, out2_g, out2_b);
    simgsmn_main<<<BB, 512>>>(inp1, inp2, out);
}

// round 2
// speedup vs baseline: 1.7584x; 1.7584x over previous
#include <cuda_runtime.h>
#include <math.h>

#define BB   2048
#define NN   36
#define EMBD 1024
#define SIMD 16
#define HID  32
#define KK   8

// Folded head parameters (written by prep kernel each launch — deterministic).
__device__ float g_Wc[SIMD * HID];   // Wc[d*32+h] = (sum_j Wsum[d][j] * v1[h][j]) * scale[h]
__device__ float g_b1[HID];
__device__ float g_w2[HID];
__device__ float g_b2;

// Fully parallel fold: 1 block, 512 threads.
__global__ __launch_bounds__(512)
void prep_kernel(const float* __restrict__ gcn_w,
                 const float* __restrict__ out1_v,
                 const float* __restrict__ out1_g,
                 const float* __restrict__ out1_b,
                 const float* __restrict__ out2_v,
                 const float* __restrict__ out2_g,
                 const float* __restrict__ out2_b) {
    __shared__ float s_wsum[SIMD * HID];   // sum_k gcn_w[k][d][j]  (512)
    __shared__ float s_v[HID * HID];       // out1_v               (1024)
    __shared__ float s_scale[HID];

    const int t = threadIdx.x;

    // Wsum[t] = sum_k gcn_w[k*512 + t]  -- 8 coalesced loads
    float ws = 0.f;
    #pragma unroll
    for (int k = 0; k < KK; k++) ws += gcn_w[k * (SIMD * HID) + t];
    s_wsum[t] = ws;

    // stage out1_v (1024 floats, 2 per thread)
    s_v[t]       = out1_v[t];
    s_v[t + 512] = out1_v[t + 512];
    __syncthreads();

    if (t < HID) {
        float nrm = 0.f;
        #pragma unroll
        for (int j = 0; j < HID; j++) { float v = s_v[t * HID + j]; nrm += v * v; }
        s_scale[t] = out1_g[t] / (sqrtf(nrm) + 1e-12f);
    }
    __syncthreads();

    // Wc entry per thread: t -> (d = t>>5, h = t&31)
    {
        const int d = t >> 5, h = t & 31;
        float acc = 0.f;
        #pragma unroll
        for (int j = 0; j < HID; j++)
            acc += s_wsum[d * HID + j] * s_v[h * HID + j];
        g_Wc[d * HID + h] = acc * s_scale[h];
    }

    if (t < HID) {
        g_b1[t] = out1_b[t];
        float n2 = 0.f;
        #pragma unroll
        for (int j = 0; j < HID; j++) { float v = out2_v[j]; n2 += v * v; }
        g_w2[t] = out2_g[0] * out2_v[t] / (sqrtf(n2) + 1e-12f);
        if (t == 0) g_b2 = out2_b[0];
    }
}

__global__ __launch_bounds__(256, 5)
void simgsmn_main(const float* __restrict__ inp1,
                  const float* __restrict__ inp2,
                  float* __restrict__ out) {
    const int b    = blockIdx.x;
    const int tid  = threadIdx.x;
    const int lane = tid & 31;
    const int warp = tid >> 5;

    __shared__ float s_sim[NN][SIMD];
    __shared__ float s_Wc[SIMD * HID];
    __shared__ float s_b1[HID];
    __shared__ float s_w2[HID];
    __shared__ float s_partial[8];

    // stage folded weights (256 threads -> 2 Wc entries each)
    s_Wc[tid]       = g_Wc[tid];
    s_Wc[tid + 256] = g_Wc[tid + 256];
    if (tid < HID) { s_b1[tid] = g_b1[tid]; s_w2[tid] = g_w2[tid]; }

    const float* p1 = inp1 + (size_t)b * (NN * EMBD);
    const float* p2 = inp2 + (size_t)b * (NN * EMBD);

    // ---- phase 1: block-wise cosine sim -> s_sim[i][d] ----
    // 256 threads cover one full row (1024 floats) per input per iteration.
    // 16 threads per 64-elem sim block; unroll 2 rows for MLP=4.
    const int d = tid >> 4;  // 0..15
    #pragma unroll 1
    for (int i0 = 0; i0 < NN; i0 += 2) {
        const int off0 = (i0 + 0) * EMBD + tid * 4;
        const int off1 = (i0 + 1) * EMBD + tid * 4;
        const float4 q0 = *reinterpret_cast<const float4*>(p1 + off0);
        const float4 c0 = *reinterpret_cast<const float4*>(p2 + off0);
        const float4 q1 = *reinterpret_cast<const float4*>(p1 + off1);
        const float4 c1 = *reinterpret_cast<const float4*>(p2 + off1);

        float dqc0 = q0.x * c0.x + q0.y * c0.y + q0.z * c0.z + q0.w * c0.w;
        float nq0  = q0.x * q0.x + q0.y * q0.y + q0.z * q0.z + q0.w * q0.w;
        float nc0  = c0.x * c0.x + c0.y * c0.y + c0.z * c0.z + c0.w * c0.w;
        float dqc1 = q1.x * c1.x + q1.y * c1.y + q1.z * c1.z + q1.w * c1.w;
        float nq1  = q1.x * q1.x + q1.y * q1.y + q1.z * q1.z + q1.w * q1.w;
        float nc1  = c1.x * c1.x + c1.y * c1.y + c1.z * c1.z + c1.w * c1.w;

        #pragma unroll
        for (int o = 8; o > 0; o >>= 1) {
            dqc0 += __shfl_xor_sync(0xFFFFFFFFu, dqc0, o);
            nq0  += __shfl_xor_sync(0xFFFFFFFFu, nq0,  o);
            nc0  += __shfl_xor_sync(0xFFFFFFFFu, nc0,  o);
            dqc1 += __shfl_xor_sync(0xFFFFFFFFu, dqc1, o);
            nq1  += __shfl_xor_sync(0xFFFFFFFFu, nq1,  o);
            nc1  += __shfl_xor_sync(0xFFFFFFFFu, nc1,  o);
        }
        if ((lane & 15) == 0) {
            s_sim[i0 + 0][d] = dqc0 / ((sqrtf(nq0) + 1e-8f) * (sqrtf(nc0) + 1e-8f));
            s_sim[i0 + 1][d] = dqc1 / ((sqrtf(nq1) + 1e-8f) * (sqrtf(nc1) + 1e-8f));
        }
    }
    __syncthreads();

    // ---- phase 2: per-row MLP head, warp per row ----
    float wsum = 0.f;
    for (int i = warp; i < NN; i += 8) {
        float acc = s_b1[lane];
        #pragma unroll
        for (int dd = 0; dd < SIMD; dd++)
            acc += s_sim[i][dd] * s_Wc[dd * HID + lane];
        float p = tanhf(acc) * s_w2[lane];
        #pragma unroll
        for (int o = 16; o > 0; o >>= 1)
            p += __shfl_xor_sync(0xFFFFFFFFu, p, o);
        wsum += p;
    }
    if (lane == 0) s_partial[warp] = wsum;
    __syncthreads();

    if (warp == 0) {
        float v = (lane < 8) ? s_partial[lane] : 0.f;
        #pragma unroll
        for (int o = 4; o > 0; o >>= 1)
            v += __shfl_xor_sync(0xFFFFFFFFu, v, o);
        if (lane == 0) out[b] = v * (1.0f / NN) + g_b2;
    }
}

extern "C" void kernel_launch(void* const* d_in, const int* in_sizes, int n_in,
                              void* d_out, int out_size) {
    const float* inp1   = (const float*)d_in[0];
    const float* inp2   = (const float*)d_in[1];
    // d_in[2]=gk_mean, d_in[3]=gk_prec: unused — Gaussian branch collapses to
    // sum_j w_norm = S/(S+1e-8) = 1 - O(1e-7), below output tolerance.
    const float* gcn_w  = (const float*)d_in[4];
    const float* out1_v = (const float*)d_in[5];
    const float* out1_g = (const float*)d_in[6];
    const float* out1_b = (const float*)d_in[7];
    const float* out2_v = (const float*)d_in[8];
    const float* out2_g = (const float*)d_in[9];
    const float* out2_b = (const float*)d_in[10];
    float* out = (float*)d_out;

    prep_kernel<<<1, 512>>>(gcn_w, out1_v, out1_g, out1_b, out2_v, out2_g, out2_b);
    simgsmn_main<<<BB, 256>>>(inp1, inp2, out);
}

// round 5
// speedup vs baseline: 2.1858x; 1.2430x over previous
#include <cuda_runtime.h>
#include <math.h>

#define BB   2048
#define NN   36
#define EMBD 1024
#define SIMD 16
#define HID  32
#define KK   8

__global__ __launch_bounds__(256, 5)
void simgsmn_fused(const float* __restrict__ inp1,
                   const float* __restrict__ inp2,
                   const float* __restrict__ gcn_w,
                   const float* __restrict__ out1_v,
                   const float* __restrict__ out1_g,
                   const float* __restrict__ out1_b,
                   const float* __restrict__ out2_v,
                   const float* __restrict__ out2_g,
                   const float* __restrict__ out2_b,
                   float* __restrict__ out) {
    const int b    = blockIdx.x;
    const int tid  = threadIdx.x;
    const int lane = tid & 31;
    const int warp = tid >> 5;

    __shared__ float s_sim[NN][SIMD];
    __shared__ float s_Wc[SIMD * HID];
    __shared__ float s_wsum[SIMD * HID];
    __shared__ float s_v[HID * 33];       // padded stride-33: conflict-free v[h][j] reads
    __shared__ float s_scale[HID];
    __shared__ float s_b1[HID];
    __shared__ float s_w2[HID];
    __shared__ float s_partial[8];
    __shared__ float s_b2;

    const float* p1 = inp1 + (size_t)b * (NN * EMBD);
    const float* p2 = inp2 + (size_t)b * (NN * EMBD);

    // ---- phase 1: block-wise cosine sim -> s_sim[i][d] ----
    // 128 threads per row: 16 sim-blocks x 8 threads. Thread loads 2 float4
    // per input from its block (at +0 and +32 floats). Each warp LDG.128
    // covers 4 full 128B lines. 3-level butterfly within 8-thread groups.
    const int rhalf = tid >> 7;      // which row of the pair
    const int r     = tid & 127;
    const int d     = r >> 3;        // sim block 0..15
    const int u     = r & 7;         // thread within block

    const int boff = d * 64 + u * 4;

    #pragma unroll 2
    for (int it = 0; it < NN / 2; it++) {
        const int i = 2 * it + rhalf;
        const float4* qp = reinterpret_cast<const float4*>(p1 + i * EMBD + boff);
        const float4* cp = reinterpret_cast<const float4*>(p2 + i * EMBD + boff);
        const float4 qa = __ldcs(qp);
        const float4 qb = __ldcs(qp + 8);   // +32 floats
        const float4 ca = __ldcs(cp);
        const float4 cb = __ldcs(cp + 8);

        float dqc = qa.x * ca.x + qa.y * ca.y + qa.z * ca.z + qa.w * ca.w
                  + qb.x * cb.x + qb.y * cb.y + qb.z * cb.z + qb.w * cb.w;
        float nq  = qa.x * qa.x + qa.y * qa.y + qa.z * qa.z + qa.w * qa.w
                  + qb.x * qb.x + qb.y * qb.y + qb.z * qb.z + qb.w * qb.w;
        float nc  = ca.x * ca.x + ca.y * ca.y + ca.z * ca.z + ca.w * ca.w
                  + cb.x * cb.x + cb.y * cb.y + cb.z * cb.z + cb.w * cb.w;

        #pragma unroll
        for (int o = 4; o > 0; o >>= 1) {
            dqc += __shfl_xor_sync(0xFFFFFFFFu, dqc, o);
            nq  += __shfl_xor_sync(0xFFFFFFFFu, nq,  o);
            nc  += __shfl_xor_sync(0xFFFFFFFFu, nc,  o);
        }
        if (u == 0)
            s_sim[i][d] = dqc / ((sqrtf(nq) + 1e-8f) * (sqrtf(nc) + 1e-8f));
    }
    __syncthreads();

    // ---- phase 1.5: fold weights in-CTA (L2-hot after first wave) ----
    // Wsum[d][j] = sum_k gcn_w[k][d][j]; stage out1_v padded.
    {
        float ws0 = 0.f, ws1 = 0.f;
        #pragma unroll
        for (int k = 0; k < KK; k++) {
            ws0 += gcn_w[k * (SIMD * HID) + tid];
            ws1 += gcn_w[k * (SIMD * HID) + tid + 256];
        }
        s_wsum[tid]       = ws0;
        s_wsum[tid + 256] = ws1;

        #pragma unroll
        for (int m = 0; m < 4; m++) {
            const int e = tid + 256 * m;
            s_v[(e >> 5) * 33 + (e & 31)] = out1_v[e];
        }
    }
    __syncthreads();

    if (tid < HID) {
        float nrm = 0.f;
        #pragma unroll
        for (int j = 0; j < HID; j++) { float v = s_v[tid * 33 + j]; nrm += v * v; }
        s_scale[tid] = out1_g[tid] / (sqrtf(nrm) + 1e-12f);
        s_b1[tid] = out1_b[tid];

        float n2 = 0.f;
        #pragma unroll
        for (int j = 0; j < HID; j++) { float v = out2_v[j]; n2 += v * v; }
        s_w2[tid] = out2_g[0] * out2_v[tid] / (sqrtf(n2) + 1e-12f);
        if (tid == 0) s_b2 = out2_b[0];
    }
    __syncthreads();

    // Wc[d][h] = scale[h] * sum_j Wsum[d][j] * v[h][j]   (2 entries/thread)
    #pragma unroll
    for (int m = 0; m < 2; m++) {
        const int e  = tid + 256 * m;
        const int dd = e >> 5, h = e & 31;
        float acc = 0.f;
        #pragma unroll
        for (int j = 0; j < HID; j++)
            acc += s_wsum[dd * HID + j] * s_v[h * 33 + j];
        s_Wc[e] = acc * s_scale[h];
    }
    __syncthreads();

    // ---- phase 2: per-row MLP head, warp per row ----
    float wsum = 0.f;
    for (int i = warp; i < NN; i += 8) {
        float acc = s_b1[lane];
        #pragma unroll
        for (int dd = 0; dd < SIMD; dd++)
            acc += s_sim[i][dd] * s_Wc[dd * HID + lane];
        float p = tanhf(acc) * s_w2[lane];
        #pragma unroll
        for (int o = 16; o > 0; o >>= 1)
            p += __shfl_xor_sync(0xFFFFFFFFu, p, o);
        wsum += p;
    }
    if (lane == 0) s_partial[warp] = wsum;
    __syncthreads();

    if (warp == 0) {
        float v = (lane < 8) ? s_partial[lane] : 0.f;
        #pragma unroll
        for (int o = 4; o > 0; o >>= 1)
            v += __shfl_xor_sync(0xFFFFFFFFu, v, o);
        if (lane == 0) out[b] = v * (1.0f / NN) + s_b2;
    }
}

extern "C" void kernel_launch(void* const* d_in, const int* in_sizes, int n_in,
                              void* d_out, int out_size) {
    const float* inp1   = (const float*)d_in[0];
    const float* inp2   = (const float*)d_in[1];
    // d_in[2]=gk_mean, d_in[3]=gk_prec: unused — Gaussian branch collapses to
    // sum_j w_norm = S/(S+1e-8) = 1 - O(1e-7), below output tolerance.
    const float* gcn_w  = (const float*)d_in[4];
    const float* out1_v = (const float*)d_in[5];
    const float* out1_g = (const float*)d_in[6];
    const float* out1_b = (const float*)d_in[7];
    const float* out2_v = (const float*)d_in[8];
    const float* out2_g = (const float*)d_in[9];
    const float* out2_b = (const float*)d_in[10];
    float* out = (float*)d_out;

    simgsmn_fused<<<BB, 256>>>(inp1, inp2, gcn_w, out1_v, out1_g, out1_b,
                               out2_v, out2_g, out2_b, out);
}